// round 10
// baseline (speedup 1.0000x reference)
#include <cuda_runtime.h>
#include <cuda_bf16.h>
#include <cuda_fp16.h>
#include <cstdint>

#define NN   50000
#define EE   800000
#define HH   4
#define CC   64
#define DIN  128
#define D1   256

// ---------------- device scratch ----------------
__device__ __half g_xs[NN * D1];        // fp16 messages (xs = X @ Wsrc)
__device__ float  g_acc[NN * D1];       // layer-1 skip accumulator (float)
__device__ __half g_hh[NN * D1];        // hidden after LN+ReLU (fp16)
__device__ float  g_asad[NN * 8];       // layer-1 scores: a_s[0..3], a_d[0..3]
__device__ float  g_asad2[NN * 8];      // layer-2 scores (separate: no RAW race)
__device__ float  g_vcat1[DIN * 8];     // layer-1 folded att vectors
__device__ float  g_vcat2[D1 * 8];      // layer-2 folded att vectors
__device__ int    g_deg[NN];
__device__ int    g_rowptr[NN + 1];
__device__ int    g_cursor[NN];
__device__ int    g_csrc[EE];           // CSR position -> src node

// ---------------- CSR build ----------------
__global__ void k_count(const int* __restrict__ dst) {
    int t = blockIdx.x * blockDim.x + threadIdx.x;
    if (t < EE) atomicAdd(&g_deg[dst[t]], 1);
}

__global__ void k_scan() {
    __shared__ int sums[1024];
    int t = threadIdx.x;
    const int CH = (NN + 1023) / 1024;
    int base = t * CH;
    int s = 0;
    for (int i = 0; i < CH; i++) {
        int idx = base + i;
        if (idx < NN) s += g_deg[idx];
    }
    int my = s;
    sums[t] = s;
    __syncthreads();
    for (int d = 1; d < 1024; d <<= 1) {
        int v = (t >= d) ? sums[t - d] : 0;
        __syncthreads();
        sums[t] += v;
        __syncthreads();
    }
    if (t == 1023) g_rowptr[NN] = sums[1023];
    int off = sums[t] - my;
    for (int i = 0; i < CH; i++) {
        int idx = base + i;
        if (idx < NN) {
            g_rowptr[idx] = off;
            g_cursor[idx] = off;
            off += g_deg[idx];
        }
    }
}

__global__ void k_fill(const int* __restrict__ dst, const int* __restrict__ src) {
    int t = blockIdx.x * blockDim.x + threadIdx.x;
    if (t < EE) {
        int p = atomicAdd(&g_cursor[dst[t]], 1);
        g_csrc[p] = src[t];
    }
}

// ---------------- fold att vectors, both layers, warp per output ----------------
__global__ void k_vcat_all(const float* __restrict__ Wsrc1, const float* __restrict__ Wdst1,
                           const float* __restrict__ atts1, const float* __restrict__ attd1,
                           const float* __restrict__ Wsrc2, const float* __restrict__ Wdst2,
                           const float* __restrict__ atts2, const float* __restrict__ attd2) {
    int wrp = (blockIdx.x * blockDim.x + threadIdx.x) >> 5;
    int l = threadIdx.x & 31;
    const int TOT = (DIN + D1) * 8;
    if (wrp >= TOT) return;
    const float* W;
    const float* att;
    float* outp;
    int t = wrp;
    if (t < DIN * 8) {
        int j = t & 7;
        W = (j < 4) ? Wsrc1 : Wdst1;
        att = (j < 4) ? atts1 : attd1;
        outp = g_vcat1;
    } else {
        t -= DIN * 8;
        int j = t & 7;
        W = (j < 4) ? Wsrc2 : Wdst2;
        att = (j < 4) ? atts2 : attd2;
        outp = g_vcat2;
    }
    int k = t >> 3, j = t & 7, h = j & 3;
    float s = W[k * D1 + h * CC + l] * att[h * CC + l]
            + W[k * D1 + h * CC + l + 32] * att[h * CC + l + 32];
#pragma unroll
    for (int d = 16; d > 0; d >>= 1) s += __shfl_xor_sync(0xFFFFFFFFu, s, d);
    if (l == 0) outp[t] = s;
}

// ---------------- fp16 MMA helper ----------------
__device__ __forceinline__ void mma_f16(float* d, const uint32_t* a, const uint32_t* b) {
    asm volatile(
        "mma.sync.aligned.m16n8k16.row.col.f32.f16.f16.f32 "
        "{%0,%1,%2,%3}, {%4,%5,%6,%7}, {%8,%9}, {%0,%1,%2,%3};"
        : "+f"(d[0]), "+f"(d[1]), "+f"(d[2]), "+f"(d[3])
        : "r"(a[0]), "r"(a[1]), "r"(a[2]), "r"(a[3]), "r"(b[0]), "r"(b[1]));
}

__device__ __forceinline__ uint32_t pack_half2(float x, float y) {
    __half2 t = __floats2half2_rn(x, y);
    return *(uint32_t*)&t;
}

// ---------------- fused dual GEMM, fp16 inputs, f32 accum (BM=128,BN=64,BK=32) ----------------
template <int K, typename TA>
__global__ void __launch_bounds__(256)
k_dualgemm(const TA* __restrict__ X,
           const float* __restrict__ W1, const float* __restrict__ W2,
           const float* __restrict__ b2a, const float* __restrict__ b2b,
           __half* __restrict__ Y1, float* __restrict__ Y2) {
    __shared__ __align__(16) uint32_t As[2][128][20];
    __shared__ __align__(16) uint32_t Bs1[2][16][72];
    __shared__ __align__(16) uint32_t Bs2[2][16][72];

    const int tid = threadIdx.x;
    const int bm = blockIdx.x * 128, bn = blockIdx.y * 64;
    const int lane = tid & 31, wid = tid >> 5;
    const int wm = wid >> 1, wn = wid & 1;
    const int gid = lane >> 2, tig = lane & 3;

    const int kp = tid >> 4, nq = tid & 15;

    float4 raf[4];
    uint4  rah[2];
    float4 rb1a, rb1b, rb2a, rb2b;

    float acc[2][2][4][4];
#pragma unroll
    for (int m = 0; m < 2; m++)
#pragma unroll
        for (int i = 0; i < 2; i++)
#pragma unroll
            for (int j = 0; j < 4; j++)
#pragma unroll
                for (int q = 0; q < 4; q++) acc[m][i][j][q] = 0.f;

    const int KT = K / 32;

    auto load_tile = [&](int k0) {
        if constexpr (sizeof(TA) == 4) {
#pragma unroll
            for (int i = 0; i < 4; i++) {
                int f = tid + i * 256;
                int row = f >> 3, seg = f & 7;
                int gr = bm + row;
                float4 v = make_float4(0.f, 0.f, 0.f, 0.f);
                if (gr < NN) v = *(const float4*)((const float*)X + (size_t)gr * K + k0 + seg * 4);
                raf[i] = v;
            }
        } else {
#pragma unroll
            for (int i = 0; i < 2; i++) {
                int f = tid + i * 256;
                int row = f >> 2, sq = f & 3;
                int gr = bm + row;
                uint4 v = make_uint4(0u, 0u, 0u, 0u);
                if (gr < NN) v = *(const uint4*)((const __half*)X + (size_t)gr * K + k0 + sq * 8);
                rah[i] = v;
            }
        }
        rb1a = *(const float4*)(W1 + (size_t)(k0 + 2 * kp) * D1 + bn + nq * 4);
        rb1b = *(const float4*)(W1 + (size_t)(k0 + 2 * kp + 1) * D1 + bn + nq * 4);
        rb2a = *(const float4*)(W2 + (size_t)(k0 + 2 * kp) * D1 + bn + nq * 4);
        rb2b = *(const float4*)(W2 + (size_t)(k0 + 2 * kp + 1) * D1 + bn + nq * 4);
    };

    auto store_tile = [&](int st) {
        if constexpr (sizeof(TA) == 4) {
#pragma unroll
            for (int i = 0; i < 4; i++) {
                int f = tid + i * 256;
                int row = f >> 3, seg = f & 7;
                uint2 h;
                h.x = pack_half2(raf[i].x, raf[i].y);
                h.y = pack_half2(raf[i].z, raf[i].w);
                *(uint2*)&As[st][row][seg * 2] = h;
            }
        } else {
#pragma unroll
            for (int i = 0; i < 2; i++) {
                int f = tid + i * 256;
                int row = f >> 2, sq = f & 3;
                *(uint4*)&As[st][row][sq * 4] = rah[i];
            }
        }
        uint4 w;
        w.x = pack_half2(rb1a.x, rb1b.x);
        w.y = pack_half2(rb1a.y, rb1b.y);
        w.z = pack_half2(rb1a.z, rb1b.z);
        w.w = pack_half2(rb1a.w, rb1b.w);
        *(uint4*)&Bs1[st][kp][nq * 4] = w;
        w.x = pack_half2(rb2a.x, rb2b.x);
        w.y = pack_half2(rb2a.y, rb2b.y);
        w.z = pack_half2(rb2a.z, rb2b.z);
        w.w = pack_half2(rb2a.w, rb2b.w);
        *(uint4*)&Bs2[st][kp][nq * 4] = w;
    };

    load_tile(0);
    store_tile(0);
    __syncthreads();

    for (int kt = 0; kt < KT; kt++) {
        const int cur = kt & 1;
        const int nxt = cur ^ 1;
        if (kt + 1 < KT) load_tile((kt + 1) * 32);

#pragma unroll
        for (int ks = 0; ks < 2; ks++) {
            uint32_t a[2][4], bf1[4][2], bf2[4][2];
#pragma unroll
            for (int mt = 0; mt < 2; mt++) {
                int mr = wm * 32 + mt * 16 + gid;
                int kw = ks * 8 + tig;
                a[mt][0] = As[cur][mr][kw];
                a[mt][1] = As[cur][mr + 8][kw];
                a[mt][2] = As[cur][mr][kw + 4];
                a[mt][3] = As[cur][mr + 8][kw + 4];
            }
#pragma unroll
            for (int nt = 0; nt < 4; nt++) {
                int nc = wn * 32 + nt * 8 + gid;
                int kq = ks * 8 + tig;
                bf1[nt][0] = Bs1[cur][kq][nc];
                bf1[nt][1] = Bs1[cur][kq + 4][nc];
                bf2[nt][0] = Bs2[cur][kq][nc];
                bf2[nt][1] = Bs2[cur][kq + 4][nc];
            }
#pragma unroll
            for (int mt = 0; mt < 2; mt++)
#pragma unroll
                for (int nt = 0; nt < 4; nt++) {
                    mma_f16(acc[0][mt][nt], a[mt], bf1[nt]);
                    mma_f16(acc[1][mt][nt], a[mt], bf2[nt]);
                }
        }

        if (kt + 1 < KT) store_tile(nxt);
        __syncthreads();
    }

#pragma unroll
    for (int mt = 0; mt < 2; mt++) {
#pragma unroll
        for (int nt = 0; nt < 4; nt++) {
            int r0 = bm + wm * 32 + mt * 16 + gid;
            int c0 = bn + wn * 32 + nt * 8 + tig * 2;
            float bb0 = b2a[c0] + b2b[c0];
            float bb1 = b2a[c0 + 1] + b2b[c0 + 1];
            if (r0 < NN) {
                __half2 h = __floats2half2_rn(acc[0][mt][nt][0], acc[0][mt][nt][1]);
                *(__half2*)(Y1 + (size_t)r0 * D1 + c0) = h;
                *(float2*)(Y2 + (size_t)r0 * D1 + c0) =
                    make_float2(acc[1][mt][nt][0] + bb0, acc[1][mt][nt][1] + bb1);
            }
            if (r0 + 8 < NN) {
                __half2 h = __floats2half2_rn(acc[0][mt][nt][2], acc[0][mt][nt][3]);
                *(__half2*)(Y1 + (size_t)(r0 + 8) * D1 + c0) = h;
                *(float2*)(Y2 + (size_t)(r0 + 8) * D1 + c0) =
                    make_float2(acc[1][mt][nt][2] + bb0, acc[1][mt][nt][3] + bb1);
            }
        }
    }
}

// ---------------- a_s/a_d layer 1: warp per node (fp32 X, vcat1) ----------------
__global__ void k_asad1(const float* __restrict__ X) {
    int w = (blockIdx.x * blockDim.x + threadIdx.x) >> 5;
    int l = threadIdx.x & 31;
    if (w >= NN) return;
    const float* xr = X + (size_t)w * DIN;
    float s[8] = {0.f, 0.f, 0.f, 0.f, 0.f, 0.f, 0.f, 0.f};
#pragma unroll
    for (int q = 0; q < DIN / 32; q++) {
        int k = l + 32 * q;
        float xv = xr[k];
        float4 v0 = *(const float4*)&g_vcat1[k * 8];
        float4 v1 = *(const float4*)&g_vcat1[k * 8 + 4];
        s[0] = fmaf(xv, v0.x, s[0]); s[1] = fmaf(xv, v0.y, s[1]);
        s[2] = fmaf(xv, v0.z, s[2]); s[3] = fmaf(xv, v0.w, s[3]);
        s[4] = fmaf(xv, v1.x, s[4]); s[5] = fmaf(xv, v1.y, s[5]);
        s[6] = fmaf(xv, v1.z, s[6]); s[7] = fmaf(xv, v1.w, s[7]);
    }
#pragma unroll
    for (int j = 0; j < 8; j++) {
#pragma unroll
        for (int d = 16; d > 0; d >>= 1) s[j] += __shfl_xor_sync(0xFFFFFFFFu, s[j], d);
    }
    if (l < 8) g_asad[w * 8 + l] = s[l];
}

// ---------------- aggregation core with inline softmax ----------------
// Softmax is shift invariant; scores are O(1) so exp cannot overflow.
__device__ __forceinline__ void agg_row(int w, int l, const __half* __restrict__ xs,
                                        const float* __restrict__ asad,
                                        float* acc, float& inv) {
    int rs = g_rowptr[w], re = g_rowptr[w + 1];
    int head = l >> 3;
    float ad = asad[w * 8 + 4 + head];
    float den = 0.f;
    int p = rs;
    for (; p + 1 < re; p += 2) {
        int s0 = g_csrc[p], s1 = g_csrc[p + 1];
        float e0 = asad[s0 * 8 + head] + ad;
        float e1 = asad[s1 * 8 + head] + ad;
        e0 = (e0 > 0.f) ? e0 : 0.2f * e0;
        e1 = (e1 > 0.f) ? e1 : 0.2f * e1;
        float a0 = __expf(e0);
        float a1 = __expf(e1);
        den += a0 + a1;
        uint4 v0 = *(const uint4*)(xs + (size_t)s0 * D1 + l * 8);
        uint4 v1 = *(const uint4*)(xs + (size_t)s1 * D1 + l * 8);
        const __half2* h0 = (const __half2*)&v0;
        const __half2* h1 = (const __half2*)&v1;
#pragma unroll
        for (int j = 0; j < 4; j++) {
            float2 f0 = __half22float2(h0[j]);
            float2 f1 = __half22float2(h1[j]);
            acc[2 * j]     = fmaf(a0, f0.x, acc[2 * j]);
            acc[2 * j + 1] = fmaf(a0, f0.y, acc[2 * j + 1]);
            acc[2 * j]     = fmaf(a1, f1.x, acc[2 * j]);
            acc[2 * j + 1] = fmaf(a1, f1.y, acc[2 * j + 1]);
        }
    }
    if (p < re) {
        int s0 = g_csrc[p];
        float e0 = asad[s0 * 8 + head] + ad;
        e0 = (e0 > 0.f) ? e0 : 0.2f * e0;
        float a0 = __expf(e0);
        den += a0;
        uint4 v0 = *(const uint4*)(xs + (size_t)s0 * D1 + l * 8);
        const __half2* h0 = (const __half2*)&v0;
#pragma unroll
        for (int j = 0; j < 4; j++) {
            float2 f0 = __half22float2(h0[j]);
            acc[2 * j]     = fmaf(a0, f0.x, acc[2 * j]);
            acc[2 * j + 1] = fmaf(a0, f0.y, acc[2 * j + 1]);
        }
    }
    inv = 1.f / (den + 1e-16f);
}

// ---------------- layer-1: aggregate + skip + LN + ReLU -> half h, + layer-2 asad ----------------
__global__ void k_agg_ln(const __half* __restrict__ xs, const float* __restrict__ skip,
                         __half* __restrict__ hout,
                         const float* __restrict__ gamma, const float* __restrict__ beta) {
    int w = (blockIdx.x * blockDim.x + threadIdx.x) >> 5;
    int l = threadIdx.x & 31;
    if (w >= NN) return;
    float m[8] = {0.f, 0.f, 0.f, 0.f, 0.f, 0.f, 0.f, 0.f};
    float inv;
    agg_row(w, l, xs, g_asad, m, inv);

    const float* sk = skip + (size_t)w * D1 + l * 8;
    float4 s0 = *(const float4*)(sk);
    float4 s1 = *(const float4*)(sk + 4);
    float v[8] = {s0.x + m[0] * inv, s0.y + m[1] * inv, s0.z + m[2] * inv, s0.w + m[3] * inv,
                  s1.x + m[4] * inv, s1.y + m[5] * inv, s1.z + m[6] * inv, s1.w + m[7] * inv};
    float sm = 0.f, sq = 0.f;
#pragma unroll
    for (int k = 0; k < 8; k++) { sm += v[k]; sq += v[k] * v[k]; }
#pragma unroll
    for (int d = 16; d > 0; d >>= 1) {
        sm += __shfl_xor_sync(0xFFFFFFFFu, sm, d);
        sq += __shfl_xor_sync(0xFFFFFFFFu, sq, d);
    }
    float mean = sm * (1.f / D1);
    float var = sq * (1.f / D1) - mean * mean;
    float rstd = rsqrtf(var + 1e-5f);
    const float* gp = gamma + l * 8;
    const float* bp = beta + l * 8;
    float4 g0 = *(const float4*)(gp);
    float4 g1 = *(const float4*)(gp + 4);
    float4 be0 = *(const float4*)(bp);
    float4 be1 = *(const float4*)(bp + 4);
    float r[8];
    r[0] = fmaxf((v[0] - mean) * rstd * g0.x + be0.x, 0.f);
    r[1] = fmaxf((v[1] - mean) * rstd * g0.y + be0.y, 0.f);
    r[2] = fmaxf((v[2] - mean) * rstd * g0.z + be0.z, 0.f);
    r[3] = fmaxf((v[3] - mean) * rstd * g0.w + be0.w, 0.f);
    r[4] = fmaxf((v[4] - mean) * rstd * g1.x + be1.x, 0.f);
    r[5] = fmaxf((v[5] - mean) * rstd * g1.y + be1.y, 0.f);
    r[6] = fmaxf((v[6] - mean) * rstd * g1.z + be1.z, 0.f);
    r[7] = fmaxf((v[7] - mean) * rstd * g1.w + be1.w, 0.f);
    uint4 hv;
    hv.x = pack_half2(r[0], r[1]);
    hv.y = pack_half2(r[2], r[3]);
    hv.z = pack_half2(r[4], r[5]);
    hv.w = pack_half2(r[6], r[7]);
    *(uint4*)(hout + (size_t)w * D1 + l * 8) = hv;

    // fused layer-2 asad -> g_asad2 (separate buffer: no race with layer-1 reads)
    float s[8] = {0.f, 0.f, 0.f, 0.f, 0.f, 0.f, 0.f, 0.f};
#pragma unroll
    for (int c = 0; c < 8; c++) {
        int k = l * 8 + c;
        float xv = r[c];
        float4 v0 = *(const float4*)&g_vcat2[k * 8];
        float4 v1 = *(const float4*)&g_vcat2[k * 8 + 4];
        s[0] = fmaf(xv, v0.x, s[0]); s[1] = fmaf(xv, v0.y, s[1]);
        s[2] = fmaf(xv, v0.z, s[2]); s[3] = fmaf(xv, v0.w, s[3]);
        s[4] = fmaf(xv, v1.x, s[4]); s[5] = fmaf(xv, v1.y, s[5]);
        s[6] = fmaf(xv, v1.z, s[6]); s[7] = fmaf(xv, v1.w, s[7]);
    }
#pragma unroll
    for (int j = 0; j < 8; j++) {
#pragma unroll
        for (int d = 16; d > 0; d >>= 1) s[j] += __shfl_xor_sync(0xFFFFFFFFu, s[j], d);
    }
    if (l < 8) g_asad2[w * 8 + l] = s[l];
}

// ---------------- layer-2: aggregate into out ----------------
__global__ void k_agg2(const __half* __restrict__ xs, float* __restrict__ out) {
    int w = (blockIdx.x * blockDim.x + threadIdx.x) >> 5;
    int l = threadIdx.x & 31;
    if (w >= NN) return;
    int rs = g_rowptr[w], re = g_rowptr[w + 1];
    if (rs == re) return;
    float m[8] = {0.f, 0.f, 0.f, 0.f, 0.f, 0.f, 0.f, 0.f};
    float inv;
    agg_row(w, l, xs, g_asad2, m, inv);
    float* o = out + (size_t)w * D1 + l * 8;
    float4 t0 = *(const float4*)(o);
    float4 t1 = *(const float4*)(o + 4);
    t0.x = fmaf(m[0], inv, t0.x); t0.y = fmaf(m[1], inv, t0.y);
    t0.z = fmaf(m[2], inv, t0.z); t0.w = fmaf(m[3], inv, t0.w);
    t1.x = fmaf(m[4], inv, t1.x); t1.y = fmaf(m[5], inv, t1.y);
    t1.z = fmaf(m[6], inv, t1.z); t1.w = fmaf(m[7], inv, t1.w);
    *(float4*)(o) = t0;
    *(float4*)(o + 4) = t1;
}

// ---------------- host launch ----------------
extern "C" void kernel_launch(void* const* d_in, const int* in_sizes, int n_in,
                              void* d_out, int out_size) {
    const float* x     = (const float*)d_in[0];
    const int*   ei    = (const int*)d_in[1];
    const float* Wsrc1 = (const float*)d_in[2];
    const float* Wdst1 = (const float*)d_in[3];
    const float* atts1 = (const float*)d_in[4];
    const float* attd1 = (const float*)d_in[5];
    const float* b1    = (const float*)d_in[6];
    const float* Wlin1 = (const float*)d_in[7];
    const float* blin1 = (const float*)d_in[8];
    const float* gamma = (const float*)d_in[9];
    const float* beta  = (const float*)d_in[10];
    const float* Wsrc2 = (const float*)d_in[11];
    const float* Wdst2 = (const float*)d_in[12];
    const float* atts2 = (const float*)d_in[13];
    const float* attd2 = (const float*)d_in[14];
    const float* b2    = (const float*)d_in[15];
    const float* Wlin2 = (const float*)d_in[16];
    const float* blin2 = (const float*)d_in[17];
    float* out = (float*)d_out;

    const int* src = ei;
    const int* dst = ei + EE;

    __half *xs_p, *hh_p;
    float* acc_p;
    int* deg_p;
    cudaGetSymbolAddress((void**)&xs_p, g_xs);
    cudaGetSymbolAddress((void**)&acc_p, g_acc);
    cudaGetSymbolAddress((void**)&hh_p, g_hh);
    cudaGetSymbolAddress((void**)&deg_p, g_deg);

    // vcat for BOTH layers, one launch ((128+256)*8 = 3072 warps)
    k_vcat_all<<<(3072 * 32 + 255) / 256, 256>>>(Wsrc1, Wdst1, atts1, attd1,
                                                 Wsrc2, Wdst2, atts2, attd2);

    // CSR (graph identical across layers)
    cudaMemsetAsync(deg_p, 0, NN * sizeof(int), 0);
    k_count<<<(EE + 255) / 256, 256>>>(dst);
    k_scan<<<1, 1024>>>();
    k_fill<<<(EE + 255) / 256, 256>>>(dst, src);

    dim3 gg((NN + 127) / 128, D1 / 64);

    // ---- layer 1 (K = 128, A fp32) ----
    k_dualgemm<DIN, float><<<gg, 256>>>(x, Wsrc1, Wlin1, blin1, b1, xs_p, acc_p);
    k_asad1<<<(NN * 32 + 255) / 256, 256>>>(x);
    k_agg_ln<<<(NN + 7) / 8, 256>>>(xs_p, acc_p, hh_p, gamma, beta);

    // ---- layer 2 (K = 256, A fp16; asad2 computed in k_agg_ln into g_asad2) ----
    k_dualgemm<D1, __half><<<gg, 256>>>(hh_p, Wsrc2, Wlin2, blin2, b2, xs_p, out);
    k_agg2<<<(NN + 7) / 8, 256>>>(xs_p, out);
}

// round 11
// speedup vs baseline: 1.1566x; 1.1566x over previous
#include <cuda_runtime.h>
#include <cuda_bf16.h>
#include <cuda_fp16.h>
#include <cstdint>

#define NN   50000
#define EE   800000
#define HH   4
#define CC   64
#define DIN  128
#define D1   256

// ---------------- device scratch ----------------
__device__ __half g_xs[NN * D1];        // fp16 messages (xs = X @ Wsrc)
__device__ float  g_acc[NN * D1];       // layer-1 skip accumulator (float)
__device__ __half g_hh[NN * D1];        // hidden after LN+ReLU (fp16)
__device__ float  g_asad[NN * 8];       // per node: a_s[0..3], a_d[0..3]
__device__ float  g_vcat1[DIN * 8];     // layer-1 folded att vectors
__device__ float  g_vcat2[D1 * 8];      // layer-2 folded att vectors
__device__ int    g_deg[NN];
__device__ int    g_rowptr[NN + 1];
__device__ int    g_cursor[NN];
__device__ int    g_csrc[EE];           // CSR position -> src node

// ---------------- CSR build ----------------
__global__ void k_count(const int* __restrict__ dst) {
    int t = blockIdx.x * blockDim.x + threadIdx.x;
    if (t < EE) atomicAdd(&g_deg[dst[t]], 1);
}

__global__ void k_scan() {
    __shared__ int sums[1024];
    int t = threadIdx.x;
    const int CH = (NN + 1023) / 1024;
    int base = t * CH;
    int s = 0;
    for (int i = 0; i < CH; i++) {
        int idx = base + i;
        if (idx < NN) s += g_deg[idx];
    }
    int my = s;
    sums[t] = s;
    __syncthreads();
    for (int d = 1; d < 1024; d <<= 1) {
        int v = (t >= d) ? sums[t - d] : 0;
        __syncthreads();
        sums[t] += v;
        __syncthreads();
    }
    if (t == 1023) g_rowptr[NN] = sums[1023];
    int off = sums[t] - my;
    for (int i = 0; i < CH; i++) {
        int idx = base + i;
        if (idx < NN) {
            g_rowptr[idx] = off;
            g_cursor[idx] = off;
            off += g_deg[idx];
        }
    }
}

__global__ void k_fill(const int* __restrict__ dst, const int* __restrict__ src) {
    int t = blockIdx.x * blockDim.x + threadIdx.x;
    if (t < EE) {
        int p = atomicAdd(&g_cursor[dst[t]], 1);
        g_csrc[p] = src[t];
    }
}

// ---------------- fold att vectors, both layers, one launch, warp per output ----------------
__global__ void k_vcat_all(const float* __restrict__ Wsrc1, const float* __restrict__ Wdst1,
                           const float* __restrict__ atts1, const float* __restrict__ attd1,
                           const float* __restrict__ Wsrc2, const float* __restrict__ Wdst2,
                           const float* __restrict__ atts2, const float* __restrict__ attd2) {
    int wrp = (blockIdx.x * blockDim.x + threadIdx.x) >> 5;
    int l = threadIdx.x & 31;
    const int TOT = (DIN + D1) * 8;
    if (wrp >= TOT) return;
    const float* W;
    const float* att;
    float* outp;
    int t = wrp;
    if (t < DIN * 8) {
        int j = t & 7;
        W = (j < 4) ? Wsrc1 : Wdst1;
        att = (j < 4) ? atts1 : attd1;
        outp = g_vcat1;
    } else {
        t -= DIN * 8;
        int j = t & 7;
        W = (j < 4) ? Wsrc2 : Wdst2;
        att = (j < 4) ? atts2 : attd2;
        outp = g_vcat2;
    }
    int k = t >> 3, j = t & 7, h = j & 3;
    float s = W[k * D1 + h * CC + l] * att[h * CC + l]
            + W[k * D1 + h * CC + l + 32] * att[h * CC + l + 32];
#pragma unroll
    for (int d = 16; d > 0; d >>= 1) s += __shfl_xor_sync(0xFFFFFFFFu, s, d);
    if (l == 0) outp[t] = s;
}

// ---------------- fp16 MMA helper ----------------
__device__ __forceinline__ void mma_f16(float* d, const uint32_t* a, const uint32_t* b) {
    asm volatile(
        "mma.sync.aligned.m16n8k16.row.col.f32.f16.f16.f32 "
        "{%0,%1,%2,%3}, {%4,%5,%6,%7}, {%8,%9}, {%0,%1,%2,%3};"
        : "+f"(d[0]), "+f"(d[1]), "+f"(d[2]), "+f"(d[3])
        : "r"(a[0]), "r"(a[1]), "r"(a[2]), "r"(a[3]), "r"(b[0]), "r"(b[1]));
}

__device__ __forceinline__ uint32_t pack_half2(float x, float y) {
    __half2 t = __floats2half2_rn(x, y);
    return *(uint32_t*)&t;
}

// ---------------- fused dual GEMM, fp16 inputs, f32 accum (BM=128,BN=64,BK=32) ----------------
template <int K, typename TA>
__global__ void __launch_bounds__(256)
k_dualgemm(const TA* __restrict__ X,
           const float* __restrict__ W1, const float* __restrict__ W2,
           const float* __restrict__ b2a, const float* __restrict__ b2b,
           __half* __restrict__ Y1, float* __restrict__ Y2) {
    __shared__ __align__(16) uint32_t As[2][128][20];
    __shared__ __align__(16) uint32_t Bs1[2][16][72];
    __shared__ __align__(16) uint32_t Bs2[2][16][72];

    const int tid = threadIdx.x;
    const int bm = blockIdx.x * 128, bn = blockIdx.y * 64;
    const int lane = tid & 31, wid = tid >> 5;
    const int wm = wid >> 1, wn = wid & 1;
    const int gid = lane >> 2, tig = lane & 3;

    const int kp = tid >> 4, nq = tid & 15;

    float4 raf[4];
    uint4  rah[2];
    float4 rb1a, rb1b, rb2a, rb2b;

    float acc[2][2][4][4];
#pragma unroll
    for (int m = 0; m < 2; m++)
#pragma unroll
        for (int i = 0; i < 2; i++)
#pragma unroll
            for (int j = 0; j < 4; j++)
#pragma unroll
                for (int q = 0; q < 4; q++) acc[m][i][j][q] = 0.f;

    const int KT = K / 32;

    auto load_tile = [&](int k0) {
        if constexpr (sizeof(TA) == 4) {
#pragma unroll
            for (int i = 0; i < 4; i++) {
                int f = tid + i * 256;
                int row = f >> 3, seg = f & 7;
                int gr = bm + row;
                float4 v = make_float4(0.f, 0.f, 0.f, 0.f);
                if (gr < NN) v = *(const float4*)((const float*)X + (size_t)gr * K + k0 + seg * 4);
                raf[i] = v;
            }
        } else {
#pragma unroll
            for (int i = 0; i < 2; i++) {
                int f = tid + i * 256;
                int row = f >> 2, sq = f & 3;
                int gr = bm + row;
                uint4 v = make_uint4(0u, 0u, 0u, 0u);
                if (gr < NN) v = *(const uint4*)((const __half*)X + (size_t)gr * K + k0 + sq * 8);
                rah[i] = v;
            }
        }
        rb1a = *(const float4*)(W1 + (size_t)(k0 + 2 * kp) * D1 + bn + nq * 4);
        rb1b = *(const float4*)(W1 + (size_t)(k0 + 2 * kp + 1) * D1 + bn + nq * 4);
        rb2a = *(const float4*)(W2 + (size_t)(k0 + 2 * kp) * D1 + bn + nq * 4);
        rb2b = *(const float4*)(W2 + (size_t)(k0 + 2 * kp + 1) * D1 + bn + nq * 4);
    };

    auto store_tile = [&](int st) {
        if constexpr (sizeof(TA) == 4) {
#pragma unroll
            for (int i = 0; i < 4; i++) {
                int f = tid + i * 256;
                int row = f >> 3, seg = f & 7;
                uint2 h;
                h.x = pack_half2(raf[i].x, raf[i].y);
                h.y = pack_half2(raf[i].z, raf[i].w);
                *(uint2*)&As[st][row][seg * 2] = h;
            }
        } else {
#pragma unroll
            for (int i = 0; i < 2; i++) {
                int f = tid + i * 256;
                int row = f >> 2, sq = f & 3;
                *(uint4*)&As[st][row][sq * 4] = rah[i];
            }
        }
        uint4 w;
        w.x = pack_half2(rb1a.x, rb1b.x);
        w.y = pack_half2(rb1a.y, rb1b.y);
        w.z = pack_half2(rb1a.z, rb1b.z);
        w.w = pack_half2(rb1a.w, rb1b.w);
        *(uint4*)&Bs1[st][kp][nq * 4] = w;
        w.x = pack_half2(rb2a.x, rb2b.x);
        w.y = pack_half2(rb2a.y, rb2b.y);
        w.z = pack_half2(rb2a.z, rb2b.z);
        w.w = pack_half2(rb2a.w, rb2b.w);
        *(uint4*)&Bs2[st][kp][nq * 4] = w;
    };

    load_tile(0);
    store_tile(0);
    __syncthreads();

    for (int kt = 0; kt < KT; kt++) {
        const int cur = kt & 1;
        const int nxt = cur ^ 1;
        if (kt + 1 < KT) load_tile((kt + 1) * 32);

#pragma unroll
        for (int ks = 0; ks < 2; ks++) {
            uint32_t a[2][4], bf1[4][2], bf2[4][2];
#pragma unroll
            for (int mt = 0; mt < 2; mt++) {
                int mr = wm * 32 + mt * 16 + gid;
                int kw = ks * 8 + tig;
                a[mt][0] = As[cur][mr][kw];
                a[mt][1] = As[cur][mr + 8][kw];
                a[mt][2] = As[cur][mr][kw + 4];
                a[mt][3] = As[cur][mr + 8][kw + 4];
            }
#pragma unroll
            for (int nt = 0; nt < 4; nt++) {
                int nc = wn * 32 + nt * 8 + gid;
                int kq = ks * 8 + tig;
                bf1[nt][0] = Bs1[cur][kq][nc];
                bf1[nt][1] = Bs1[cur][kq + 4][nc];
                bf2[nt][0] = Bs2[cur][kq][nc];
                bf2[nt][1] = Bs2[cur][kq + 4][nc];
            }
#pragma unroll
            for (int mt = 0; mt < 2; mt++)
#pragma unroll
                for (int nt = 0; nt < 4; nt++) {
                    mma_f16(acc[0][mt][nt], a[mt], bf1[nt]);
                    mma_f16(acc[1][mt][nt], a[mt], bf2[nt]);
                }
        }

        if (kt + 1 < KT) store_tile(nxt);
        __syncthreads();
    }

#pragma unroll
    for (int mt = 0; mt < 2; mt++) {
#pragma unroll
        for (int nt = 0; nt < 4; nt++) {
            int r0 = bm + wm * 32 + mt * 16 + gid;
            int c0 = bn + wn * 32 + nt * 8 + tig * 2;
            float bb0 = b2a[c0] + b2b[c0];
            float bb1 = b2a[c0 + 1] + b2b[c0 + 1];
            if (r0 < NN) {
                __half2 h = __floats2half2_rn(acc[0][mt][nt][0], acc[0][mt][nt][1]);
                *(__half2*)(Y1 + (size_t)r0 * D1 + c0) = h;
                *(float2*)(Y2 + (size_t)r0 * D1 + c0) =
                    make_float2(acc[1][mt][nt][0] + bb0, acc[1][mt][nt][1] + bb1);
            }
            if (r0 + 8 < NN) {
                __half2 h = __floats2half2_rn(acc[0][mt][nt][2], acc[0][mt][nt][3]);
                *(__half2*)(Y1 + (size_t)(r0 + 8) * D1 + c0) = h;
                *(float2*)(Y2 + (size_t)(r0 + 8) * D1 + c0) =
                    make_float2(acc[1][mt][nt][2] + bb0, acc[1][mt][nt][3] + bb1);
            }
        }
    }
}

// ---------------- a_s/a_d: warp per node (LAYER selects vcat buffer) ----------------
template <int K, typename TA, int LAYER>
__global__ void k_asad(const TA* __restrict__ X) {
    int w = (blockIdx.x * blockDim.x + threadIdx.x) >> 5;
    int l = threadIdx.x & 31;
    if (w >= NN) return;
    const float* vc = (LAYER == 1) ? g_vcat1 : g_vcat2;
    const TA* xr = X + (size_t)w * K;
    float s[8] = {0.f, 0.f, 0.f, 0.f, 0.f, 0.f, 0.f, 0.f};
#pragma unroll
    for (int q = 0; q < K / 32; q++) {
        int k = l + 32 * q;
        float xv;
        if constexpr (sizeof(TA) == 4) xv = (float)xr[k];
        else                           xv = __half2float(xr[k]);
        float4 v0 = *(const float4*)&vc[k * 8];
        float4 v1 = *(const float4*)&vc[k * 8 + 4];
        s[0] = fmaf(xv, v0.x, s[0]); s[1] = fmaf(xv, v0.y, s[1]);
        s[2] = fmaf(xv, v0.z, s[2]); s[3] = fmaf(xv, v0.w, s[3]);
        s[4] = fmaf(xv, v1.x, s[4]); s[5] = fmaf(xv, v1.y, s[5]);
        s[6] = fmaf(xv, v1.z, s[6]); s[7] = fmaf(xv, v1.w, s[7]);
    }
#pragma unroll
    for (int j = 0; j < 8; j++) {
#pragma unroll
        for (int d = 16; d > 0; d >>= 1) s[j] += __shfl_xor_sync(0xFFFFFFFFu, s[j], d);
    }
    if (l < 8) g_asad[w * 8 + l] = s[l];
}

// ---------------- aggregation core with inline softmax ----------------
// Softmax is shift invariant; scores are O(1) so exp cannot overflow.
__device__ __forceinline__ void agg_row(int w, int l, const __half* __restrict__ xs,
                                        float* acc, float& inv) {
    int rs = g_rowptr[w], re = g_rowptr[w + 1];
    int head = l >> 3;
    float ad = g_asad[w * 8 + 4 + head];
    float den = 0.f;
    int p = rs;
    for (; p + 1 < re; p += 2) {
        int s0 = g_csrc[p], s1 = g_csrc[p + 1];
        float e0 = g_asad[s0 * 8 + head] + ad;
        float e1 = g_asad[s1 * 8 + head] + ad;
        e0 = (e0 > 0.f) ? e0 : 0.2f * e0;
        e1 = (e1 > 0.f) ? e1 : 0.2f * e1;
        float a0 = __expf(e0);
        float a1 = __expf(e1);
        den += a0 + a1;
        uint4 v0 = *(const uint4*)(xs + (size_t)s0 * D1 + l * 8);
        uint4 v1 = *(const uint4*)(xs + (size_t)s1 * D1 + l * 8);
        const __half2* h0 = (const __half2*)&v0;
        const __half2* h1 = (const __half2*)&v1;
#pragma unroll
        for (int j = 0; j < 4; j++) {
            float2 f0 = __half22float2(h0[j]);
            float2 f1 = __half22float2(h1[j]);
            acc[2 * j]     = fmaf(a0, f0.x, acc[2 * j]);
            acc[2 * j + 1] = fmaf(a0, f0.y, acc[2 * j + 1]);
            acc[2 * j]     = fmaf(a1, f1.x, acc[2 * j]);
            acc[2 * j + 1] = fmaf(a1, f1.y, acc[2 * j + 1]);
        }
    }
    if (p < re) {
        int s0 = g_csrc[p];
        float e0 = g_asad[s0 * 8 + head] + ad;
        e0 = (e0 > 0.f) ? e0 : 0.2f * e0;
        float a0 = __expf(e0);
        den += a0;
        uint4 v0 = *(const uint4*)(xs + (size_t)s0 * D1 + l * 8);
        const __half2* h0 = (const __half2*)&v0;
#pragma unroll
        for (int j = 0; j < 4; j++) {
            float2 f0 = __half22float2(h0[j]);
            acc[2 * j]     = fmaf(a0, f0.x, acc[2 * j]);
            acc[2 * j + 1] = fmaf(a0, f0.y, acc[2 * j + 1]);
        }
    }
    inv = 1.f / (den + 1e-16f);
}

// ---------------- layer-1: aggregate + skip + LayerNorm + ReLU -> half h ----------------
__global__ void k_agg_ln(const __half* __restrict__ xs, const float* __restrict__ skip,
                         __half* __restrict__ hout,
                         const float* __restrict__ gamma, const float* __restrict__ beta) {
    int w = (blockIdx.x * blockDim.x + threadIdx.x) >> 5;
    int l = threadIdx.x & 31;
    if (w >= NN) return;
    float m[8] = {0.f, 0.f, 0.f, 0.f, 0.f, 0.f, 0.f, 0.f};
    float inv;
    agg_row(w, l, xs, m, inv);

    const float* sk = skip + (size_t)w * D1 + l * 8;
    float4 s0 = *(const float4*)(sk);
    float4 s1 = *(const float4*)(sk + 4);
    float v[8] = {s0.x + m[0] * inv, s0.y + m[1] * inv, s0.z + m[2] * inv, s0.w + m[3] * inv,
                  s1.x + m[4] * inv, s1.y + m[5] * inv, s1.z + m[6] * inv, s1.w + m[7] * inv};
    float sm = 0.f, sq = 0.f;
#pragma unroll
    for (int k = 0; k < 8; k++) { sm += v[k]; sq += v[k] * v[k]; }
#pragma unroll
    for (int d = 16; d > 0; d >>= 1) {
        sm += __shfl_xor_sync(0xFFFFFFFFu, sm, d);
        sq += __shfl_xor_sync(0xFFFFFFFFu, sq, d);
    }
    float mean = sm * (1.f / D1);
    float var = sq * (1.f / D1) - mean * mean;
    float rstd = rsqrtf(var + 1e-5f);
    const float* gp = gamma + l * 8;
    const float* bp = beta + l * 8;
    float4 g0 = *(const float4*)(gp);
    float4 g1 = *(const float4*)(gp + 4);
    float4 be0 = *(const float4*)(bp);
    float4 be1 = *(const float4*)(bp + 4);
    float r[8];
    r[0] = fmaxf((v[0] - mean) * rstd * g0.x + be0.x, 0.f);
    r[1] = fmaxf((v[1] - mean) * rstd * g0.y + be0.y, 0.f);
    r[2] = fmaxf((v[2] - mean) * rstd * g0.z + be0.z, 0.f);
    r[3] = fmaxf((v[3] - mean) * rstd * g0.w + be0.w, 0.f);
    r[4] = fmaxf((v[4] - mean) * rstd * g1.x + be1.x, 0.f);
    r[5] = fmaxf((v[5] - mean) * rstd * g1.y + be1.y, 0.f);
    r[6] = fmaxf((v[6] - mean) * rstd * g1.z + be1.z, 0.f);
    r[7] = fmaxf((v[7] - mean) * rstd * g1.w + be1.w, 0.f);
    uint4 hv;
    hv.x = pack_half2(r[0], r[1]);
    hv.y = pack_half2(r[2], r[3]);
    hv.z = pack_half2(r[4], r[5]);
    hv.w = pack_half2(r[6], r[7]);
    *(uint4*)(hout + (size_t)w * D1 + l * 8) = hv;
}

// ---------------- layer-2: aggregate into out ----------------
__global__ void k_agg2(const __half* __restrict__ xs, float* __restrict__ out) {
    int w = (blockIdx.x * blockDim.x + threadIdx.x) >> 5;
    int l = threadIdx.x & 31;
    if (w >= NN) return;
    int rs = g_rowptr[w], re = g_rowptr[w + 1];
    if (rs == re) return;
    float m[8] = {0.f, 0.f, 0.f, 0.f, 0.f, 0.f, 0.f, 0.f};
    float inv;
    agg_row(w, l, xs, m, inv);
    float* o = out + (size_t)w * D1 + l * 8;
    float4 t0 = *(const float4*)(o);
    float4 t1 = *(const float4*)(o + 4);
    t0.x = fmaf(m[0], inv, t0.x); t0.y = fmaf(m[1], inv, t0.y);
    t0.z = fmaf(m[2], inv, t0.z); t0.w = fmaf(m[3], inv, t0.w);
    t1.x = fmaf(m[4], inv, t1.x); t1.y = fmaf(m[5], inv, t1.y);
    t1.z = fmaf(m[6], inv, t1.z); t1.w = fmaf(m[7], inv, t1.w);
    *(float4*)(o) = t0;
    *(float4*)(o + 4) = t1;
}

// ---------------- host launch ----------------
extern "C" void kernel_launch(void* const* d_in, const int* in_sizes, int n_in,
                              void* d_out, int out_size) {
    const float* x     = (const float*)d_in[0];
    const int*   ei    = (const int*)d_in[1];
    const float* Wsrc1 = (const float*)d_in[2];
    const float* Wdst1 = (const float*)d_in[3];
    const float* atts1 = (const float*)d_in[4];
    const float* attd1 = (const float*)d_in[5];
    const float* b1    = (const float*)d_in[6];
    const float* Wlin1 = (const float*)d_in[7];
    const float* blin1 = (const float*)d_in[8];
    const float* gamma = (const float*)d_in[9];
    const float* beta  = (const float*)d_in[10];
    const float* Wsrc2 = (const float*)d_in[11];
    const float* Wdst2 = (const float*)d_in[12];
    const float* atts2 = (const float*)d_in[13];
    const float* attd2 = (const float*)d_in[14];
    const float* b2    = (const float*)d_in[15];
    const float* Wlin2 = (const float*)d_in[16];
    const float* blin2 = (const float*)d_in[17];
    float* out = (float*)d_out;

    const int* src = ei;
    const int* dst = ei + EE;

    __half *xs_p, *hh_p;
    float* acc_p;
    int* deg_p;
    cudaGetSymbolAddress((void**)&xs_p, g_xs);
    cudaGetSymbolAddress((void**)&acc_p, g_acc);
    cudaGetSymbolAddress((void**)&hh_p, g_hh);
    cudaGetSymbolAddress((void**)&deg_p, g_deg);

    // vcat for BOTH layers, one launch ((128+256)*8 = 3072 warps)
    k_vcat_all<<<(3072 * 32 + 255) / 256, 256>>>(Wsrc1, Wdst1, atts1, attd1,
                                                 Wsrc2, Wdst2, atts2, attd2);

    // CSR (graph identical across layers)
    cudaMemsetAsync(deg_p, 0, NN * sizeof(int), 0);
    k_count<<<(EE + 255) / 256, 256>>>(dst);
    k_scan<<<1, 1024>>>();
    k_fill<<<(EE + 255) / 256, 256>>>(dst, src);

    dim3 gg((NN + 127) / 128, D1 / 64);

    // ---- layer 1 (K = 128, A fp32) ----
    k_dualgemm<DIN, float><<<gg, 256>>>(x, Wsrc1, Wlin1, blin1, b1, xs_p, acc_p);
    k_asad<DIN, float, 1><<<(NN * 32 + 255) / 256, 256>>>(x);
    k_agg_ln<<<(NN + 7) / 8, 256>>>(xs_p, acc_p, hh_p, gamma, beta);

    // ---- layer 2 (K = 256, A fp16) ----
    k_dualgemm<D1, __half><<<gg, 256>>>(hh_p, Wsrc2, Wlin2, blin2, b2, xs_p, out);
    k_asad<D1, __half, 2><<<(NN * 32 + 255) / 256, 256>>>(hh_p);
    k_agg2<<<(NN + 7) / 8, 256>>>(xs_p, out);
}

// round 13
// speedup vs baseline: 1.1705x; 1.0121x over previous
#include <cuda_runtime.h>
#include <cuda_bf16.h>
#include <cuda_fp16.h>
#include <cstdint>

#define NN   50000
#define EE   800000
#define HH   4
#define CC   64
#define DIN  128
#define D1   256

// ---------------- device scratch ----------------
__device__ __half   g_xs[NN * D1];       // fp16 messages (xs = X @ Wsrc)
__device__ float    g_acc[NN * D1];      // layer-1 skip accumulator (float)
__device__ __half   g_hh[NN * D1];       // hidden after LN+ReLU (fp16)
__device__ __half   g_xh[NN * DIN];      // fp16 copy of x (GEMM A path)
__device__ float    g_asad[NN * 8];      // per node: a_s[0..3], a_d[0..3]
__device__ float    g_vcat1[DIN * 8];
__device__ float    g_vcat2[D1 * 8];
__device__ uint32_t g_w1i[(DIN / 2) * D1];   // Wsrc1 k-pair-interleaved fp16
__device__ uint32_t g_w1bi[(DIN / 2) * D1];  // Wlin1
__device__ uint32_t g_w2i[(D1 / 2) * D1];    // Wsrc2
__device__ uint32_t g_w2bi[(D1 / 2) * D1];   // Wlin2
__device__ int      g_deg[NN];
__device__ int      g_rowptr[NN + 1];
__device__ int      g_cursor[NN];
__device__ int      g_csrc[EE];          // CSR position -> src node

// ---------------- CSR build ----------------
__global__ void k_count(const int* __restrict__ dst) {
    int t = blockIdx.x * blockDim.x + threadIdx.x;
    if (t < EE) atomicAdd(&g_deg[dst[t]], 1);
}

__global__ void k_scan() {
    __shared__ int sums[1024];
    int t = threadIdx.x;
    const int CH = (NN + 1023) / 1024;
    int base = t * CH;
    int s = 0;
    for (int i = 0; i < CH; i++) {
        int idx = base + i;
        if (idx < NN) s += g_deg[idx];
    }
    int my = s;
    sums[t] = s;
    __syncthreads();
    for (int d = 1; d < 1024; d <<= 1) {
        int v = (t >= d) ? sums[t - d] : 0;
        __syncthreads();
        sums[t] += v;
        __syncthreads();
    }
    if (t == 1023) g_rowptr[NN] = sums[1023];
    int off = sums[t] - my;
    for (int i = 0; i < CH; i++) {
        int idx = base + i;
        if (idx < NN) {
            g_rowptr[idx] = off;
            g_cursor[idx] = off;
            off += g_deg[idx];
        }
    }
}

__global__ void k_fill(const int* __restrict__ dst, const int* __restrict__ src) {
    int t = blockIdx.x * blockDim.x + threadIdx.x;
    if (t < EE) {
        int p = atomicAdd(&g_cursor[dst[t]], 1);
        g_csrc[p] = src[t];
    }
}

// ---------------- fold att vectors, both layers, one launch, warp per output ----------------
__global__ void k_vcat_all(const float* __restrict__ Wsrc1, const float* __restrict__ Wdst1,
                           const float* __restrict__ atts1, const float* __restrict__ attd1,
                           const float* __restrict__ Wsrc2, const float* __restrict__ Wdst2,
                           const float* __restrict__ atts2, const float* __restrict__ attd2) {
    int wrp = (blockIdx.x * blockDim.x + threadIdx.x) >> 5;
    int l = threadIdx.x & 31;
    const int TOT = (DIN + D1) * 8;
    if (wrp >= TOT) return;
    const float* W;
    const float* att;
    float* outp;
    int t = wrp;
    if (t < DIN * 8) {
        int j = t & 7;
        W = (j < 4) ? Wsrc1 : Wdst1;
        att = (j < 4) ? atts1 : attd1;
        outp = g_vcat1;
    } else {
        t -= DIN * 8;
        int j = t & 7;
        W = (j < 4) ? Wsrc2 : Wdst2;
        att = (j < 4) ? atts2 : attd2;
        outp = g_vcat2;
    }
    int k = t >> 3, j = t & 7, h = j & 3;
    float s = W[k * D1 + h * CC + l] * att[h * CC + l]
            + W[k * D1 + h * CC + l + 32] * att[h * CC + l + 32];
#pragma unroll
    for (int d = 16; d > 0; d >>= 1) s += __shfl_xor_sync(0xFFFFFFFFu, s, d);
    if (l == 0) outp[t] = s;
}

__device__ __forceinline__ uint32_t pack_half2(float x, float y) {
    __half2 t = __floats2half2_rn(x, y);
    return *(uint32_t*)&t;
}

// ---------------- preconvert x -> fp16 ----------------
__global__ void k_cvt_x(const float* __restrict__ x) {
    int f = blockIdx.x * blockDim.x + threadIdx.x;
    if (f >= NN * DIN / 4) return;
    float4 v = *(const float4*)(x + (size_t)f * 4);
    uint2 h;
    h.x = pack_half2(v.x, v.y);
    h.y = pack_half2(v.z, v.w);
    *(uint2*)((uint32_t*)g_xh + (size_t)f * 2) = h;
}

// ---------------- preconvert W -> k-pair-interleaved fp16 ----------------
// out[kp*256 + c] = half2(W[2kp][c], W[2kp+1][c])
__global__ void k_cvt_w(const float* __restrict__ Wsrc1, const float* __restrict__ Wlin1,
                        const float* __restrict__ Wsrc2, const float* __restrict__ Wlin2) {
    int t = blockIdx.x * blockDim.x + threadIdx.x;
    const float* W;
    uint32_t* O;
    int idx;
    if (t < 16384)       { W = Wsrc1; O = g_w1i;  idx = t; }
    else if (t < 32768)  { W = Wlin1; O = g_w1bi; idx = t - 16384; }
    else if (t < 65536)  { W = Wsrc2; O = g_w2i;  idx = t - 32768; }
    else if (t < 98304)  { W = Wlin2; O = g_w2bi; idx = t - 65536; }
    else return;
    int kp = idx >> 8, c = idx & 255;
    O[idx] = pack_half2(W[(size_t)(2 * kp) * D1 + c], W[(size_t)(2 * kp + 1) * D1 + c]);
}

// ---------------- fp16 MMA helper ----------------
__device__ __forceinline__ void mma_f16(float* d, const uint32_t* a, const uint32_t* b) {
    asm volatile(
        "mma.sync.aligned.m16n8k16.row.col.f32.f16.f16.f32 "
        "{%0,%1,%2,%3}, {%4,%5,%6,%7}, {%8,%9}, {%0,%1,%2,%3};"
        : "+f"(d[0]), "+f"(d[1]), "+f"(d[2]), "+f"(d[3])
        : "r"(a[0]), "r"(a[1]), "r"(a[2]), "r"(a[3]), "r"(b[0]), "r"(b[1]));
}

__device__ __forceinline__ void cp_async16(void* smem_dst, const void* gsrc, int sz) {
    uint32_t d = (uint32_t)__cvta_generic_to_shared(smem_dst);
    asm volatile("cp.async.cg.shared.global [%0], [%1], 16, %2;"
                 :: "r"(d), "l"(gsrc), "r"(sz) : "memory");
}

// ---------------- fused dual GEMM: fp16 A + interleaved fp16 W, cp.async 3-stage ----------------
// Y1 = X @ W1 -> half; Y2 = X @ W2 + b2a + b2b -> float
#define GEMM_SMEM_WORDS (3 * (128 * 20 + 16 * 72 * 2))
template <int K>
__global__ void __launch_bounds__(256)
k_dualgemm(const __half* __restrict__ Xh,
           const uint32_t* __restrict__ W1i, const uint32_t* __restrict__ W2i,
           const float* __restrict__ b2a, const float* __restrict__ b2b,
           __half* __restrict__ Y1, float* __restrict__ Y2) {
    extern __shared__ uint32_t smem[];
    uint32_t (*As)[128][20]  = (uint32_t(*)[128][20])smem;
    uint32_t (*Bs1)[16][72]  = (uint32_t(*)[16][72])(smem + 3 * 128 * 20);
    uint32_t (*Bs2)[16][72]  = (uint32_t(*)[16][72])(smem + 3 * 128 * 20 + 3 * 16 * 72);

    const int tid = threadIdx.x;
    const int bm = blockIdx.x * 128, bn = blockIdx.y * 64;
    const int lane = tid & 31, wid = tid >> 5;
    const int wm = wid >> 1, wn = wid & 1;
    const int gid = lane >> 2, tig = lane & 3;

    float acc[2][2][4][4];
#pragma unroll
    for (int m = 0; m < 2; m++)
#pragma unroll
        for (int i = 0; i < 2; i++)
#pragma unroll
            for (int j = 0; j < 4; j++)
#pragma unroll
                for (int q = 0; q < 4; q++) acc[m][i][j][q] = 0.f;

    const int KT = K / 32;

    // A: 512 chunks/tile -> 2/thread; B1,B2: 256 chunks each -> 1/thread each
    const int arow = tid >> 2, ac4 = tid & 3;         // chunk f = tid (+256)
    const int bkp = tid >> 4, bc16 = tid & 15;

    auto issue = [&](int kt) {
        int st = kt % 3;
        int k0 = kt * 32;       // halves for A
        int kpb = kt * 16;      // k-pair rows for B
#pragma unroll
        for (int i = 0; i < 2; i++) {
            int f = tid + i * 256;
            int row = f >> 2, c4 = f & 3;
            int gr = bm + row;
            const __half* src = Xh + (size_t)(gr < NN ? gr : 0) * K + k0 + c4 * 8;
            cp_async16(&As[st][row][c4 * 4], src, (gr < NN) ? 16 : 0);
        }
        cp_async16(&Bs1[st][bkp][bc16 * 4], W1i + (size_t)(kpb + bkp) * D1 + bn + bc16 * 4, 16);
        cp_async16(&Bs2[st][bkp][bc16 * 4], W2i + (size_t)(kpb + bkp) * D1 + bn + bc16 * 4, 16);
        asm volatile("cp.async.commit_group;" ::: "memory");
    };

    issue(0);
    issue(1);

    for (int kt = 0; kt < KT; kt++) {
        const int cur = kt % 3;
        asm volatile("cp.async.wait_group 1;" ::: "memory");
        __syncthreads();
        if (kt + 2 < KT) issue(kt + 2);
        else asm volatile("cp.async.commit_group;" ::: "memory");   // empty group keeps counting uniform

#pragma unroll
        for (int ks = 0; ks < 2; ks++) {
            uint32_t a[2][4], bf1[4][2], bf2[4][2];
#pragma unroll
            for (int mt = 0; mt < 2; mt++) {
                int mr = wm * 32 + mt * 16 + gid;
                int kw = ks * 8 + tig;
                a[mt][0] = As[cur][mr][kw];
                a[mt][1] = As[cur][mr + 8][kw];
                a[mt][2] = As[cur][mr][kw + 4];
                a[mt][3] = As[cur][mr + 8][kw + 4];
            }
#pragma unroll
            for (int nt = 0; nt < 4; nt++) {
                int nc = wn * 32 + nt * 8 + gid;
                int kq = ks * 8 + tig;
                bf1[nt][0] = Bs1[cur][kq][nc];
                bf1[nt][1] = Bs1[cur][kq + 4][nc];
                bf2[nt][0] = Bs2[cur][kq][nc];
                bf2[nt][1] = Bs2[cur][kq + 4][nc];
            }
#pragma unroll
            for (int mt = 0; mt < 2; mt++)
#pragma unroll
                for (int nt = 0; nt < 4; nt++) {
                    mma_f16(acc[0][mt][nt], a[mt], bf1[nt]);
                    mma_f16(acc[1][mt][nt], a[mt], bf2[nt]);
                }
        }
    }

#pragma unroll
    for (int mt = 0; mt < 2; mt++) {
#pragma unroll
        for (int nt = 0; nt < 4; nt++) {
            int r0 = bm + wm * 32 + mt * 16 + gid;
            int c0 = bn + wn * 32 + nt * 8 + tig * 2;
            float bb0 = b2a[c0] + b2b[c0];
            float bb1 = b2a[c0 + 1] + b2b[c0 + 1];
            if (r0 < NN) {
                __half2 h = __floats2half2_rn(acc[0][mt][nt][0], acc[0][mt][nt][1]);
                *(__half2*)(Y1 + (size_t)r0 * D1 + c0) = h;
                *(float2*)(Y2 + (size_t)r0 * D1 + c0) =
                    make_float2(acc[1][mt][nt][0] + bb0, acc[1][mt][nt][1] + bb1);
            }
            if (r0 + 8 < NN) {
                __half2 h = __floats2half2_rn(acc[0][mt][nt][2], acc[0][mt][nt][3]);
                *(__half2*)(Y1 + (size_t)(r0 + 8) * D1 + c0) = h;
                *(float2*)(Y2 + (size_t)(r0 + 8) * D1 + c0) =
                    make_float2(acc[1][mt][nt][2] + bb0, acc[1][mt][nt][3] + bb1);
            }
        }
    }
}

// ---------------- a_s/a_d: warp per node (LAYER selects vcat buffer) ----------------
template <int K, typename TA, int LAYER>
__global__ void k_asad(const TA* __restrict__ X) {
    int w = (blockIdx.x * blockDim.x + threadIdx.x) >> 5;
    int l = threadIdx.x & 31;
    if (w >= NN) return;
    const float* vc = (LAYER == 1) ? g_vcat1 : g_vcat2;
    const TA* xr = X + (size_t)w * K;
    float s[8] = {0.f, 0.f, 0.f, 0.f, 0.f, 0.f, 0.f, 0.f};
#pragma unroll
    for (int q = 0; q < K / 32; q++) {
        int k = l + 32 * q;
        float xv;
        if constexpr (sizeof(TA) == 4) xv = (float)xr[k];
        else                           xv = __half2float(xr[k]);
        float4 v0 = *(const float4*)&vc[k * 8];
        float4 v1 = *(const float4*)&vc[k * 8 + 4];
        s[0] = fmaf(xv, v0.x, s[0]); s[1] = fmaf(xv, v0.y, s[1]);
        s[2] = fmaf(xv, v0.z, s[2]); s[3] = fmaf(xv, v0.w, s[3]);
        s[4] = fmaf(xv, v1.x, s[4]); s[5] = fmaf(xv, v1.y, s[5]);
        s[6] = fmaf(xv, v1.z, s[6]); s[7] = fmaf(xv, v1.w, s[7]);
    }
#pragma unroll
    for (int j = 0; j < 8; j++) {
#pragma unroll
        for (int d = 16; d > 0; d >>= 1) s[j] += __shfl_xor_sync(0xFFFFFFFFu, s[j], d);
    }
    if (l < 8) g_asad[w * 8 + l] = s[l];
}

// ---------------- aggregation core with inline softmax ----------------
__device__ __forceinline__ void agg_row(int w, int l, const __half* __restrict__ xs,
                                        float* acc, float& inv) {
    int rs = g_rowptr[w], re = g_rowptr[w + 1];
    int head = l >> 3;
    float ad = g_asad[w * 8 + 4 + head];
    float den = 0.f;
    int p = rs;
    for (; p + 1 < re; p += 2) {
        int s0 = g_csrc[p], s1 = g_csrc[p + 1];
        float e0 = g_asad[s0 * 8 + head] + ad;
        float e1 = g_asad[s1 * 8 + head] + ad;
        e0 = (e0 > 0.f) ? e0 : 0.2f * e0;
        e1 = (e1 > 0.f) ? e1 : 0.2f * e1;
        float a0 = __expf(e0);
        float a1 = __expf(e1);
        den += a0 + a1;
        uint4 v0 = *(const uint4*)(xs + (size_t)s0 * D1 + l * 8);
        uint4 v1 = *(const uint4*)(xs + (size_t)s1 * D1 + l * 8);
        const __half2* h0 = (const __half2*)&v0;
        const __half2* h1 = (const __half2*)&v1;
#pragma unroll
        for (int j = 0; j < 4; j++) {
            float2 f0 = __half22float2(h0[j]);
            float2 f1 = __half22float2(h1[j]);
            acc[2 * j]     = fmaf(a0, f0.x, acc[2 * j]);
            acc[2 * j + 1] = fmaf(a0, f0.y, acc[2 * j + 1]);
            acc[2 * j]     = fmaf(a1, f1.x, acc[2 * j]);
            acc[2 * j + 1] = fmaf(a1, f1.y, acc[2 * j + 1]);
        }
    }
    if (p < re) {
        int s0 = g_csrc[p];
        float e0 = g_asad[s0 * 8 + head] + ad;
        e0 = (e0 > 0.f) ? e0 : 0.2f * e0;
        float a0 = __expf(e0);
        den += a0;
        uint4 v0 = *(const uint4*)(xs + (size_t)s0 * D1 + l * 8);
        const __half2* h0 = (const __half2*)&v0;
#pragma unroll
        for (int j = 0; j < 4; j++) {
            float2 f0 = __half22float2(h0[j]);
            acc[2 * j]     = fmaf(a0, f0.x, acc[2 * j]);
            acc[2 * j + 1] = fmaf(a0, f0.y, acc[2 * j + 1]);
        }
    }
    inv = 1.f / (den + 1e-16f);
}

// ---------------- layer-1: aggregate + skip + LayerNorm + ReLU -> half h ----------------
__global__ void k_agg_ln(const __half* __restrict__ xs, const float* __restrict__ skip,
                         __half* __restrict__ hout,
                         const float* __restrict__ gamma, const float* __restrict__ beta) {
    int w = (blockIdx.x * blockDim.x + threadIdx.x) >> 5;
    int l = threadIdx.x & 31;
    if (w >= NN) return;
    float m[8] = {0.f, 0.f, 0.f, 0.f, 0.f, 0.f, 0.f, 0.f};
    float inv;
    agg_row(w, l, xs, m, inv);

    const float* sk = skip + (size_t)w * D1 + l * 8;
    float4 s0 = *(const float4*)(sk);
    float4 s1 = *(const float4*)(sk + 4);
    float v[8] = {s0.x + m[0] * inv, s0.y + m[1] * inv, s0.z + m[2] * inv, s0.w + m[3] * inv,
                  s1.x + m[4] * inv, s1.y + m[5] * inv, s1.z + m[6] * inv, s1.w + m[7] * inv};
    float sm = 0.f, sq = 0.f;
#pragma unroll
    for (int k = 0; k < 8; k++) { sm += v[k]; sq += v[k] * v[k]; }
#pragma unroll
    for (int d = 16; d > 0; d >>= 1) {
        sm += __shfl_xor_sync(0xFFFFFFFFu, sm, d);
        sq += __shfl_xor_sync(0xFFFFFFFFu, sq, d);
    }
    float mean = sm * (1.f / D1);
    float var = sq * (1.f / D1) - mean * mean;
    float rstd = rsqrtf(var + 1e-5f);
    const float* gp = gamma + l * 8;
    const float* bp = beta + l * 8;
    float4 g0 = *(const float4*)(gp);
    float4 g1 = *(const float4*)(gp + 4);
    float4 be0 = *(const float4*)(bp);
    float4 be1 = *(const float4*)(bp + 4);
    float r[8];
    r[0] = fmaxf((v[0] - mean) * rstd * g0.x + be0.x, 0.f);
    r[1] = fmaxf((v[1] - mean) * rstd * g0.y + be0.y, 0.f);
    r[2] = fmaxf((v[2] - mean) * rstd * g0.z + be0.z, 0.f);
    r[3] = fmaxf((v[3] - mean) * rstd * g0.w + be0.w, 0.f);
    r[4] = fmaxf((v[4] - mean) * rstd * g1.x + be1.x, 0.f);
    r[5] = fmaxf((v[5] - mean) * rstd * g1.y + be1.y, 0.f);
    r[6] = fmaxf((v[6] - mean) * rstd * g1.z + be1.z, 0.f);
    r[7] = fmaxf((v[7] - mean) * rstd * g1.w + be1.w, 0.f);
    uint4 hv;
    hv.x = pack_half2(r[0], r[1]);
    hv.y = pack_half2(r[2], r[3]);
    hv.z = pack_half2(r[4], r[5]);
    hv.w = pack_half2(r[6], r[7]);
    *(uint4*)(hout + (size_t)w * D1 + l * 8) = hv;
}

// ---------------- layer-2: aggregate into out ----------------
__global__ void k_agg2(const __half* __restrict__ xs, float* __restrict__ out) {
    int w = (blockIdx.x * blockDim.x + threadIdx.x) >> 5;
    int l = threadIdx.x & 31;
    if (w >= NN) return;
    int rs = g_rowptr[w], re = g_rowptr[w + 1];
    if (rs == re) return;
    float m[8] = {0.f, 0.f, 0.f, 0.f, 0.f, 0.f, 0.f, 0.f};
    float inv;
    agg_row(w, l, xs, m, inv);
    float* o = out + (size_t)w * D1 + l * 8;
    float4 t0 = *(const float4*)(o);
    float4 t1 = *(const float4*)(o + 4);
    t0.x = fmaf(m[0], inv, t0.x); t0.y = fmaf(m[1], inv, t0.y);
    t0.z = fmaf(m[2], inv, t0.z); t0.w = fmaf(m[3], inv, t0.w);
    t1.x = fmaf(m[4], inv, t1.x); t1.y = fmaf(m[5], inv, t1.y);
    t1.z = fmaf(m[6], inv, t1.z); t1.w = fmaf(m[7], inv, t1.w);
    *(float4*)(o) = t0;
    *(float4*)(o + 4) = t1;
}

// ---------------- host launch (single stream) ----------------
extern "C" void kernel_launch(void* const* d_in, const int* in_sizes, int n_in,
                              void* d_out, int out_size) {
    const float* x     = (const float*)d_in[0];
    const int*   ei    = (const int*)d_in[1];
    const float* Wsrc1 = (const float*)d_in[2];
    const float* Wdst1 = (const float*)d_in[3];
    const float* atts1 = (const float*)d_in[4];
    const float* attd1 = (const float*)d_in[5];
    const float* b1    = (const float*)d_in[6];
    const float* Wlin1 = (const float*)d_in[7];
    const float* blin1 = (const float*)d_in[8];
    const float* gamma = (const float*)d_in[9];
    const float* beta  = (const float*)d_in[10];
    const float* Wsrc2 = (const float*)d_in[11];
    const float* Wdst2 = (const float*)d_in[12];
    const float* atts2 = (const float*)d_in[13];
    const float* attd2 = (const float*)d_in[14];
    const float* b2    = (const float*)d_in[15];
    const float* Wlin2 = (const float*)d_in[16];
    const float* blin2 = (const float*)d_in[17];
    float* out = (float*)d_out;

    const int* src = ei;
    const int* dst = ei + EE;

    __half *xs_p, *hh_p, *xh_p;
    float* acc_p;
    int* deg_p;
    uint32_t *w1i_p, *w1bi_p, *w2i_p, *w2bi_p;
    cudaGetSymbolAddress((void**)&xs_p, g_xs);
    cudaGetSymbolAddress((void**)&acc_p, g_acc);
    cudaGetSymbolAddress((void**)&hh_p, g_hh);
    cudaGetSymbolAddress((void**)&xh_p, g_xh);
    cudaGetSymbolAddress((void**)&deg_p, g_deg);
    cudaGetSymbolAddress((void**)&w1i_p, g_w1i);
    cudaGetSymbolAddress((void**)&w1bi_p, g_w1bi);
    cudaGetSymbolAddress((void**)&w2i_p, g_w2i);
    cudaGetSymbolAddress((void**)&w2bi_p, g_w2bi);

    const int smem_bytes = GEMM_SMEM_WORDS * 4;
    cudaFuncSetAttribute(k_dualgemm<DIN>, cudaFuncAttributeMaxDynamicSharedMemorySize, smem_bytes);
    cudaFuncSetAttribute(k_dualgemm<D1>,  cudaFuncAttributeMaxDynamicSharedMemorySize, smem_bytes);

    // preprocessing
    k_vcat_all<<<(3072 * 32 + 255) / 256, 256>>>(Wsrc1, Wdst1, atts1, attd1,
                                                 Wsrc2, Wdst2, atts2, attd2);
    k_cvt_x<<<(NN * DIN / 4 + 255) / 256, 256>>>(x);
    k_cvt_w<<<(98304 + 255) / 256, 256>>>(Wsrc1, Wlin1, Wsrc2, Wlin2);

    // CSR (graph identical across layers)
    cudaMemsetAsync(deg_p, 0, NN * sizeof(int), 0);
    k_count<<<(EE + 255) / 256, 256>>>(dst);
    k_scan<<<1, 1024>>>();
    k_fill<<<(EE + 255) / 256, 256>>>(dst, src);

    dim3 gg((NN + 127) / 128, D1 / 64);

    // ---- layer 1 (K = 128) ----
    k_dualgemm<DIN><<<gg, 256, smem_bytes>>>(xh_p, w1i_p, w1bi_p, blin1, b1, xs_p, acc_p);
    k_asad<DIN, float, 1><<<(NN * 32 + 255) / 256, 256>>>(x);
    k_agg_ln<<<(NN + 7) / 8, 256>>>(xs_p, acc_p, hh_p, gamma, beta);

    // ---- layer 2 (K = 256) ----
    k_dualgemm<D1><<<gg, 256, smem_bytes>>>(hh_p, w2i_p, w2bi_p, blin2, b2, xs_p, out);
    k_asad<D1, __half, 2><<<(NN * 32 + 255) / 256, 256>>>(hh_p);
    k_agg2<<<(NN + 7) / 8, 256>>>(xs_p, out);
}

// round 16
// speedup vs baseline: 1.3554x; 1.1580x over previous
#include <cuda_runtime.h>
#include <cuda_bf16.h>
#include <cuda_fp16.h>
#include <cstdint>

#define NN   50000
#define EE   800000
#define HH   4
#define CC   64
#define DIN  128
#define D1   256
#define SCAN_BLOCKS ((NN + 255) / 256)   // 196

// ---------------- device scratch ----------------
__device__ __half   g_xs[NN * D1];       // fp16 messages (xs = X @ Wsrc)
__device__ float    g_acc[NN * D1];      // layer-1 skip accumulator (float)
__device__ __half   g_hh[NN * D1];       // hidden after LN+ReLU (fp16)
__device__ __half   g_xh[NN * DIN];      // fp16 copy of x (GEMM A path)
__device__ float    g_asad[NN * 8];      // per node: a_s[0..3], a_d[0..3]
__device__ float    g_vcat1[DIN * 8];
__device__ float    g_vcat2[D1 * 8];
__device__ uint32_t g_w1i[(DIN / 2) * D1];   // Wsrc1 k-pair-interleaved fp16
__device__ uint32_t g_w1bi[(DIN / 2) * D1];  // Wlin1
__device__ uint32_t g_w2i[(D1 / 2) * D1];    // Wsrc2
__device__ uint32_t g_w2bi[(D1 / 2) * D1];   // Wlin2
__device__ int      g_deg[NN];
__device__ int      g_rowptr[NN + 1];
__device__ int      g_cursor[NN];
__device__ int      g_bsum[256];
__device__ int      g_csrc[EE];          // CSR position -> src node

// ---------------- CSR build ----------------
__global__ void k_count(const int* __restrict__ dst) {
    int t = blockIdx.x * blockDim.x + threadIdx.x;
    if (t < EE) atomicAdd(&g_deg[dst[t]], 1);
}

// phase 1: per-block exclusive scan + block totals
__global__ void k_scan1() {
    __shared__ int sh[256];
    int n = blockIdx.x * 256 + threadIdx.x;
    int d = (n < NN) ? g_deg[n] : 0;
    sh[threadIdx.x] = d;
    __syncthreads();
#pragma unroll
    for (int o = 1; o < 256; o <<= 1) {
        int v = (threadIdx.x >= o) ? sh[threadIdx.x - o] : 0;
        __syncthreads();
        sh[threadIdx.x] += v;
        __syncthreads();
    }
    if (n < NN) g_rowptr[n] = sh[threadIdx.x] - d;       // exclusive within block
    if (threadIdx.x == 255) g_bsum[blockIdx.x] = sh[255];
}

// phase 2: scan the block totals (1 block)
__global__ void k_scan2() {
    __shared__ int sh[256];
    int t = threadIdx.x;
    int v = (t < SCAN_BLOCKS) ? g_bsum[t] : 0;
    sh[t] = v;
    __syncthreads();
#pragma unroll
    for (int o = 1; o < 256; o <<= 1) {
        int u = (t >= o) ? sh[t - o] : 0;
        __syncthreads();
        sh[t] += u;
        __syncthreads();
    }
    if (t < SCAN_BLOCKS) g_bsum[t] = sh[t] - v;          // exclusive block offset
    if (t == 255) g_rowptr[NN] = sh[255];                // total (zeros padded)
}

// phase 3: apply block offsets
__global__ void k_scan3() {
    int n = blockIdx.x * 256 + threadIdx.x;
    if (n < NN) {
        int r = g_rowptr[n] + g_bsum[blockIdx.x];
        g_rowptr[n] = r;
        g_cursor[n] = r;
    }
}

__global__ void k_fill(const int* __restrict__ dst, const int* __restrict__ src) {
    int t = blockIdx.x * blockDim.x + threadIdx.x;
    if (t < EE) {
        int p = atomicAdd(&g_cursor[dst[t]], 1);
        g_csrc[p] = src[t];
    }
}

__device__ __forceinline__ uint32_t pack_half2(float x, float y) {
    __half2 t = __floats2half2_rn(x, y);
    return *(uint32_t*)&t;
}

// ---------------- combined prep: vcat (both layers) + W interleave-convert ----------------
// blocks [0, 384): vcat warps; blocks [384, 768): W conversion
__global__ void k_prep_wv(const float* __restrict__ Wsrc1, const float* __restrict__ Wdst1,
                          const float* __restrict__ atts1, const float* __restrict__ attd1,
                          const float* __restrict__ Wsrc2, const float* __restrict__ Wdst2,
                          const float* __restrict__ atts2, const float* __restrict__ attd2,
                          const float* __restrict__ Wlin1, const float* __restrict__ Wlin2) {
    if (blockIdx.x < 384) {
        int wrp = (blockIdx.x * 256 + threadIdx.x) >> 5;
        int l = threadIdx.x & 31;
        const int TOT = (DIN + D1) * 8;
        if (wrp >= TOT) return;
        const float* W;
        const float* att;
        float* outp;
        int t = wrp;
        if (t < DIN * 8) {
            int j = t & 7;
            W = (j < 4) ? Wsrc1 : Wdst1;
            att = (j < 4) ? atts1 : attd1;
            outp = g_vcat1;
        } else {
            t -= DIN * 8;
            int j = t & 7;
            W = (j < 4) ? Wsrc2 : Wdst2;
            att = (j < 4) ? atts2 : attd2;
            outp = g_vcat2;
        }
        int k = t >> 3, j = t & 7, h = j & 3;
        float s = W[k * D1 + h * CC + l] * att[h * CC + l]
                + W[k * D1 + h * CC + l + 32] * att[h * CC + l + 32];
#pragma unroll
        for (int d = 16; d > 0; d >>= 1) s += __shfl_xor_sync(0xFFFFFFFFu, s, d);
        if (l == 0) outp[t] = s;
    } else {
        int t = (blockIdx.x - 384) * 256 + threadIdx.x;
        const float* W;
        uint32_t* O;
        int idx;
        if (t < 16384)       { W = Wsrc1; O = g_w1i;  idx = t; }
        else if (t < 32768)  { W = Wlin1; O = g_w1bi; idx = t - 16384; }
        else if (t < 65536)  { W = Wsrc2; O = g_w2i;  idx = t - 32768; }
        else if (t < 98304)  { W = Wlin2; O = g_w2bi; idx = t - 65536; }
        else return;
        int kp = idx >> 8, c = idx & 255;
        O[idx] = pack_half2(W[(size_t)(2 * kp) * D1 + c], W[(size_t)(2 * kp + 1) * D1 + c]);
    }
}

// ---------------- prep x: fp16 convert + layer-1 asad in one pass (warp/node) ----------------
__global__ void k_prep_x(const float* __restrict__ x) {
    int w = (blockIdx.x * blockDim.x + threadIdx.x) >> 5;
    int l = threadIdx.x & 31;
    if (w >= NN) return;
    const float* xr = x + (size_t)w * DIN;
    float4 v = ((const float4*)xr)[l];          // lane l: cols 4l..4l+3
    uint2 h;
    h.x = pack_half2(v.x, v.y);
    h.y = pack_half2(v.z, v.w);
    ((uint2*)(g_xh + (size_t)w * DIN))[l] = h;

    float s[8] = {0.f, 0.f, 0.f, 0.f, 0.f, 0.f, 0.f, 0.f};
    float xv[4] = {v.x, v.y, v.z, v.w};
#pragma unroll
    for (int c = 0; c < 4; c++) {
        int k = 4 * l + c;
        float4 v0 = *(const float4*)&g_vcat1[k * 8];
        float4 v1 = *(const float4*)&g_vcat1[k * 8 + 4];
        s[0] = fmaf(xv[c], v0.x, s[0]); s[1] = fmaf(xv[c], v0.y, s[1]);
        s[2] = fmaf(xv[c], v0.z, s[2]); s[3] = fmaf(xv[c], v0.w, s[3]);
        s[4] = fmaf(xv[c], v1.x, s[4]); s[5] = fmaf(xv[c], v1.y, s[5]);
        s[6] = fmaf(xv[c], v1.z, s[6]); s[7] = fmaf(xv[c], v1.w, s[7]);
    }
#pragma unroll
    for (int j = 0; j < 8; j++) {
#pragma unroll
        for (int d = 16; d > 0; d >>= 1) s[j] += __shfl_xor_sync(0xFFFFFFFFu, s[j], d);
    }
    if (l < 8) g_asad[w * 8 + l] = s[l];
}

// ---------------- fp16 MMA helper ----------------
__device__ __forceinline__ void mma_f16(float* d, const uint32_t* a, const uint32_t* b) {
    asm volatile(
        "mma.sync.aligned.m16n8k16.row.col.f32.f16.f16.f32 "
        "{%0,%1,%2,%3}, {%4,%5,%6,%7}, {%8,%9}, {%0,%1,%2,%3};"
        : "+f"(d[0]), "+f"(d[1]), "+f"(d[2]), "+f"(d[3])
        : "r"(a[0]), "r"(a[1]), "r"(a[2]), "r"(a[3]), "r"(b[0]), "r"(b[1]));
}

__device__ __forceinline__ void cp_async16(void* smem_dst, const void* gsrc, int sz) {
    uint32_t d = (uint32_t)__cvta_generic_to_shared(smem_dst);
    asm volatile("cp.async.cg.shared.global [%0], [%1], 16, %2;"
                 :: "r"(d), "l"(gsrc), "r"(sz) : "memory");
}

// ---------------- fused dual GEMM: fp16 A + interleaved fp16 W, cp.async 3-stage ----------------
#define GEMM_SMEM_WORDS (3 * (128 * 20 + 16 * 72 * 2))
template <int K>
__global__ void __launch_bounds__(256)
k_dualgemm(const __half* __restrict__ Xh,
           const uint32_t* __restrict__ W1i, const uint32_t* __restrict__ W2i,
           const float* __restrict__ b2a, const float* __restrict__ b2b,
           __half* __restrict__ Y1, float* __restrict__ Y2) {
    extern __shared__ uint32_t smem[];
    uint32_t (*As)[128][20]  = (uint32_t(*)[128][20])smem;
    uint32_t (*Bs1)[16][72]  = (uint32_t(*)[16][72])(smem + 3 * 128 * 20);
    uint32_t (*Bs2)[16][72]  = (uint32_t(*)[16][72])(smem + 3 * 128 * 20 + 3 * 16 * 72);

    const int tid = threadIdx.x;
    const int bm = blockIdx.x * 128, bn = blockIdx.y * 64;
    const int lane = tid & 31, wid = tid >> 5;
    const int wm = wid >> 1, wn = wid & 1;
    const int gid = lane >> 2, tig = lane & 3;

    float acc[2][2][4][4];
#pragma unroll
    for (int m = 0; m < 2; m++)
#pragma unroll
        for (int i = 0; i < 2; i++)
#pragma unroll
            for (int j = 0; j < 4; j++)
#pragma unroll
                for (int q = 0; q < 4; q++) acc[m][i][j][q] = 0.f;

    const int KT = K / 32;
    const int bkp = tid >> 4, bc16 = tid & 15;

    auto issue = [&](int kt) {
        int st = kt % 3;
        int k0 = kt * 32;
        int kpb = kt * 16;
#pragma unroll
        for (int i = 0; i < 2; i++) {
            int f = tid + i * 256;
            int row = f >> 2, c4 = f & 3;
            int gr = bm + row;
            const __half* src = Xh + (size_t)(gr < NN ? gr : 0) * K + k0 + c4 * 8;
            cp_async16(&As[st][row][c4 * 4], src, (gr < NN) ? 16 : 0);
        }
        cp_async16(&Bs1[st][bkp][bc16 * 4], W1i + (size_t)(kpb + bkp) * D1 + bn + bc16 * 4, 16);
        cp_async16(&Bs2[st][bkp][bc16 * 4], W2i + (size_t)(kpb + bkp) * D1 + bn + bc16 * 4, 16);
        asm volatile("cp.async.commit_group;" ::: "memory");
    };

    issue(0);
    issue(1);

    for (int kt = 0; kt < KT; kt++) {
        const int cur = kt % 3;
        asm volatile("cp.async.wait_group 1;" ::: "memory");
        __syncthreads();
        if (kt + 2 < KT) issue(kt + 2);
        else asm volatile("cp.async.commit_group;" ::: "memory");

#pragma unroll
        for (int ks = 0; ks < 2; ks++) {
            uint32_t a[2][4], bf1[4][2], bf2[4][2];
#pragma unroll
            for (int mt = 0; mt < 2; mt++) {
                int mr = wm * 32 + mt * 16 + gid;
                int kw = ks * 8 + tig;
                a[mt][0] = As[cur][mr][kw];
                a[mt][1] = As[cur][mr + 8][kw];
                a[mt][2] = As[cur][mr][kw + 4];
                a[mt][3] = As[cur][mr + 8][kw + 4];
            }
#pragma unroll
            for (int nt = 0; nt < 4; nt++) {
                int nc = wn * 32 + nt * 8 + gid;
                int kq = ks * 8 + tig;
                bf1[nt][0] = Bs1[cur][kq][nc];
                bf1[nt][1] = Bs1[cur][kq + 4][nc];
                bf2[nt][0] = Bs2[cur][kq][nc];
                bf2[nt][1] = Bs2[cur][kq + 4][nc];
            }
#pragma unroll
            for (int mt = 0; mt < 2; mt++)
#pragma unroll
                for (int nt = 0; nt < 4; nt++) {
                    mma_f16(acc[0][mt][nt], a[mt], bf1[nt]);
                    mma_f16(acc[1][mt][nt], a[mt], bf2[nt]);
                }
        }
    }

#pragma unroll
    for (int mt = 0; mt < 2; mt++) {
#pragma unroll
        for (int nt = 0; nt < 4; nt++) {
            int r0 = bm + wm * 32 + mt * 16 + gid;
            int c0 = bn + wn * 32 + nt * 8 + tig * 2;
            float bb0 = b2a[c0] + b2b[c0];
            float bb1 = b2a[c0 + 1] + b2b[c0 + 1];
            if (r0 < NN) {
                __half2 h = __floats2half2_rn(acc[0][mt][nt][0], acc[0][mt][nt][1]);
                *(__half2*)(Y1 + (size_t)r0 * D1 + c0) = h;
                *(float2*)(Y2 + (size_t)r0 * D1 + c0) =
                    make_float2(acc[1][mt][nt][0] + bb0, acc[1][mt][nt][1] + bb1);
            }
            if (r0 + 8 < NN) {
                __half2 h = __floats2half2_rn(acc[0][mt][nt][2], acc[0][mt][nt][3]);
                *(__half2*)(Y1 + (size_t)(r0 + 8) * D1 + c0) = h;
                *(float2*)(Y2 + (size_t)(r0 + 8) * D1 + c0) =
                    make_float2(acc[1][mt][nt][2] + bb0, acc[1][mt][nt][3] + bb1);
            }
        }
    }
}

// ---------------- layer-2 asad: warp per node over fp16 h ----------------
__global__ void k_asad2(const __half* __restrict__ X) {
    int w = (blockIdx.x * blockDim.x + threadIdx.x) >> 5;
    int l = threadIdx.x & 31;
    if (w >= NN) return;
    const __half* xr = X + (size_t)w * D1;
    float s[8] = {0.f, 0.f, 0.f, 0.f, 0.f, 0.f, 0.f, 0.f};
#pragma unroll
    for (int q = 0; q < D1 / 32; q++) {
        int k = l + 32 * q;
        float xv = __half2float(xr[k]);
        float4 v0 = *(const float4*)&g_vcat2[k * 8];
        float4 v1 = *(const float4*)&g_vcat2[k * 8 + 4];
        s[0] = fmaf(xv, v0.x, s[0]); s[1] = fmaf(xv, v0.y, s[1]);
        s[2] = fmaf(xv, v0.z, s[2]); s[3] = fmaf(xv, v0.w, s[3]);
        s[4] = fmaf(xv, v1.x, s[4]); s[5] = fmaf(xv, v1.y, s[5]);
        s[6] = fmaf(xv, v1.z, s[6]); s[7] = fmaf(xv, v1.w, s[7]);
    }
#pragma unroll
    for (int j = 0; j < 8; j++) {
#pragma unroll
        for (int d = 16; d > 0; d >>= 1) s[j] += __shfl_xor_sync(0xFFFFFFFFu, s[j], d);
    }
    if (l < 8) g_asad[w * 8 + l] = s[l];
}

// ---------------- aggregation core with inline softmax ----------------
__device__ __forceinline__ void agg_row(int w, int l, const __half* __restrict__ xs,
                                        float* acc, float& inv) {
    int rs = g_rowptr[w], re = g_rowptr[w + 1];
    int head = l >> 3;
    float ad = g_asad[w * 8 + 4 + head];
    float den = 0.f;
    int p = rs;
    for (; p + 1 < re; p += 2) {
        int s0 = g_csrc[p], s1 = g_csrc[p + 1];
        float e0 = g_asad[s0 * 8 + head] + ad;
        float e1 = g_asad[s1 * 8 + head] + ad;
        e0 = (e0 > 0.f) ? e0 : 0.2f * e0;
        e1 = (e1 > 0.f) ? e1 : 0.2f * e1;
        float a0 = __expf(e0);
        float a1 = __expf(e1);
        den += a0 + a1;
        uint4 v0 = *(const uint4*)(xs + (size_t)s0 * D1 + l * 8);
        uint4 v1 = *(const uint4*)(xs + (size_t)s1 * D1 + l * 8);
        const __half2* h0 = (const __half2*)&v0;
        const __half2* h1 = (const __half2*)&v1;
#pragma unroll
        for (int j = 0; j < 4; j++) {
            float2 f0 = __half22float2(h0[j]);
            float2 f1 = __half22float2(h1[j]);
            acc[2 * j]     = fmaf(a0, f0.x, acc[2 * j]);
            acc[2 * j + 1] = fmaf(a0, f0.y, acc[2 * j + 1]);
            acc[2 * j]     = fmaf(a1, f1.x, acc[2 * j]);
            acc[2 * j + 1] = fmaf(a1, f1.y, acc[2 * j + 1]);
        }
    }
    if (p < re) {
        int s0 = g_csrc[p];
        float e0 = g_asad[s0 * 8 + head] + ad;
        e0 = (e0 > 0.f) ? e0 : 0.2f * e0;
        float a0 = __expf(e0);
        den += a0;
        uint4 v0 = *(const uint4*)(xs + (size_t)s0 * D1 + l * 8);
        const __half2* h0 = (const __half2*)&v0;
#pragma unroll
        for (int j = 0; j < 4; j++) {
            float2 f0 = __half22float2(h0[j]);
            acc[2 * j]     = fmaf(a0, f0.x, acc[2 * j]);
            acc[2 * j + 1] = fmaf(a0, f0.y, acc[2 * j + 1]);
        }
    }
    inv = 1.f / (den + 1e-16f);
}

// ---------------- layer-1: aggregate + skip + LayerNorm + ReLU -> half h ----------------
__global__ void k_agg_ln(const __half* __restrict__ xs, const float* __restrict__ skip,
                         __half* __restrict__ hout,
                         const float* __restrict__ gamma, const float* __restrict__ beta) {
    int w = (blockIdx.x * blockDim.x + threadIdx.x) >> 5;
    int l = threadIdx.x & 31;
    if (w >= NN) return;
    float m[8] = {0.f, 0.f, 0.f, 0.f, 0.f, 0.f, 0.f, 0.f};
    float inv;
    agg_row(w, l, xs, m, inv);

    const float* sk = skip + (size_t)w * D1 + l * 8;
    float4 s0 = *(const float4*)(sk);
    float4 s1 = *(const float4*)(sk + 4);
    float v[8] = {s0.x + m[0] * inv, s0.y + m[1] * inv, s0.z + m[2] * inv, s0.w + m[3] * inv,
                  s1.x + m[4] * inv, s1.y + m[5] * inv, s1.z + m[6] * inv, s1.w + m[7] * inv};
    float sm = 0.f, sq = 0.f;
#pragma unroll
    for (int k = 0; k < 8; k++) { sm += v[k]; sq += v[k] * v[k]; }
#pragma unroll
    for (int d = 16; d > 0; d >>= 1) {
        sm += __shfl_xor_sync(0xFFFFFFFFu, sm, d);
        sq += __shfl_xor_sync(0xFFFFFFFFu, sq, d);
    }
    float mean = sm * (1.f / D1);
    float var = sq * (1.f / D1) - mean * mean;
    float rstd = rsqrtf(var + 1e-5f);
    const float* gp = gamma + l * 8;
    const float* bp = beta + l * 8;
    float4 g0 = *(const float4*)(gp);
    float4 g1 = *(const float4*)(gp + 4);
    float4 be0 = *(const float4*)(bp);
    float4 be1 = *(const float4*)(bp + 4);
    float r[8];
    r[0] = fmaxf((v[0] - mean) * rstd * g0.x + be0.x, 0.f);
    r[1] = fmaxf((v[1] - mean) * rstd * g0.y + be0.y, 0.f);
    r[2] = fmaxf((v[2] - mean) * rstd * g0.z + be0.z, 0.f);
    r[3] = fmaxf((v[3] - mean) * rstd * g0.w + be0.w, 0.f);
    r[4] = fmaxf((v[4] - mean) * rstd * g1.x + be1.x, 0.f);
    r[5] = fmaxf((v[5] - mean) * rstd * g1.y + be1.y, 0.f);
    r[6] = fmaxf((v[6] - mean) * rstd * g1.z + be1.z, 0.f);
    r[7] = fmaxf((v[7] - mean) * rstd * g1.w + be1.w, 0.f);
    uint4 hv;
    hv.x = pack_half2(r[0], r[1]);
    hv.y = pack_half2(r[2], r[3]);
    hv.z = pack_half2(r[4], r[5]);
    hv.w = pack_half2(r[6], r[7]);
    *(uint4*)(hout + (size_t)w * D1 + l * 8) = hv;
}

// ---------------- layer-2: aggregate into out ----------------
__global__ void k_agg2(const __half* __restrict__ xs, float* __restrict__ out) {
    int w = (blockIdx.x * blockDim.x + threadIdx.x) >> 5;
    int l = threadIdx.x & 31;
    if (w >= NN) return;
    int rs = g_rowptr[w], re = g_rowptr[w + 1];
    if (rs == re) return;
    float m[8] = {0.f, 0.f, 0.f, 0.f, 0.f, 0.f, 0.f, 0.f};
    float inv;
    agg_row(w, l, xs, m, inv);
    float* o = out + (size_t)w * D1 + l * 8;
    float4 t0 = *(const float4*)(o);
    float4 t1 = *(const float4*)(o + 4);
    t0.x = fmaf(m[0], inv, t0.x); t0.y = fmaf(m[1], inv, t0.y);
    t0.z = fmaf(m[2], inv, t0.z); t0.w = fmaf(m[3], inv, t0.w);
    t1.x = fmaf(m[4], inv, t1.x); t1.y = fmaf(m[5], inv, t1.y);
    t1.z = fmaf(m[6], inv, t1.z); t1.w = fmaf(m[7], inv, t1.w);
    *(float4*)(o) = t0;
    *(float4*)(o + 4) = t1;
}

// ---------------- host launch (single stream) ----------------
extern "C" void kernel_launch(void* const* d_in, const int* in_sizes, int n_in,
                              void* d_out, int out_size) {
    const float* x     = (const float*)d_in[0];
    const int*   ei    = (const int*)d_in[1];
    const float* Wsrc1 = (const float*)d_in[2];
    const float* Wdst1 = (const float*)d_in[3];
    const float* atts1 = (const float*)d_in[4];
    const float* attd1 = (const float*)d_in[5];
    const float* b1    = (const float*)d_in[6];
    const float* Wlin1 = (const float*)d_in[7];
    const float* blin1 = (const float*)d_in[8];
    const float* gamma = (const float*)d_in[9];
    const float* beta  = (const float*)d_in[10];
    const float* Wsrc2 = (const float*)d_in[11];
    const float* Wdst2 = (const float*)d_in[12];
    const float* atts2 = (const float*)d_in[13];
    const float* attd2 = (const float*)d_in[14];
    const float* b2    = (const float*)d_in[15];
    const float* Wlin2 = (const float*)d_in[16];
    const float* blin2 = (const float*)d_in[17];
    float* out = (float*)d_out;

    const int* src = ei;
    const int* dst = ei + EE;

    __half *xs_p, *hh_p, *xh_p;
    float* acc_p;
    int* deg_p;
    uint32_t *w1i_p, *w1bi_p, *w2i_p, *w2bi_p;
    cudaGetSymbolAddress((void**)&xs_p, g_xs);
    cudaGetSymbolAddress((void**)&acc_p, g_acc);
    cudaGetSymbolAddress((void**)&hh_p, g_hh);
    cudaGetSymbolAddress((void**)&xh_p, g_xh);
    cudaGetSymbolAddress((void**)&deg_p, g_deg);
    cudaGetSymbolAddress((void**)&w1i_p, g_w1i);
    cudaGetSymbolAddress((void**)&w1bi_p, g_w1bi);
    cudaGetSymbolAddress((void**)&w2i_p, g_w2i);
    cudaGetSymbolAddress((void**)&w2bi_p, g_w2bi);

    const int smem_bytes = GEMM_SMEM_WORDS * 4;
    cudaFuncSetAttribute(k_dualgemm<DIN>, cudaFuncAttributeMaxDynamicSharedMemorySize, smem_bytes);
    cudaFuncSetAttribute(k_dualgemm<D1>,  cudaFuncAttributeMaxDynamicSharedMemorySize, smem_bytes);

    // preprocessing: vcat + W-interleave in one launch; then x convert + asad1 in one pass
    k_prep_wv<<<768, 256>>>(Wsrc1, Wdst1, atts1, attd1, Wsrc2, Wdst2, atts2, attd2,
                            Wlin1, Wlin2);
    k_prep_x<<<(NN * 32 + 255) / 256, 256>>>(x);

    // CSR (graph identical across layers): count -> 3-phase parallel scan -> fill
    cudaMemsetAsync(deg_p, 0, NN * sizeof(int), 0);
    k_count<<<(EE + 255) / 256, 256>>>(dst);
    k_scan1<<<SCAN_BLOCKS, 256>>>();
    k_scan2<<<1, 256>>>();
    k_scan3<<<SCAN_BLOCKS, 256>>>();
    k_fill<<<(EE + 255) / 256, 256>>>(dst, src);

    dim3 gg((NN + 127) / 128, D1 / 64);

    // ---- layer 1 (K = 128) ----
    k_dualgemm<DIN><<<gg, 256, smem_bytes>>>(xh_p, w1i_p, w1bi_p, blin1, b1, xs_p, acc_p);
    k_agg_ln<<<(NN + 7) / 8, 256>>>(xs_p, acc_p, hh_p, gamma, beta);

    // ---- layer 2 (K = 256) ----
    k_dualgemm<D1><<<gg, 256, smem_bytes>>>(hh_p, w2i_p, w2bi_p, blin2, b2, xs_p, out);
    k_asad2<<<(NN * 32 + 255) / 256, 256>>>(hh_p);
    k_agg2<<<(NN + 7) / 8, 256>>>(xs_p, out);
}